// round 1
// baseline (speedup 1.0000x reference)
#include <cuda_runtime.h>
#include <math.h>

// Problem dims
#define T_   4
#define B_   16
#define NN_  1024
#define C_   512
#define H_   8
#define D_   64
#define M_   65536        // T*B*N
#define BNC_ 8388608      // B*N*C
#define RPT_ 16384        // rows per T step (B*N)
#define QC_  1536         // fused QKV output columns

// Scratch (device globals; no allocation allowed)
__device__ float g_xs[(size_t)M_ * C_];
__device__ float g_y [(size_t)M_ * QC_];
__device__ float g_q [(size_t)M_ * C_];
__device__ float g_k [(size_t)M_ * C_];
__device__ float g_v [(size_t)M_ * C_];
__device__ float g_kvpart[(size_t)T_ * B_ * 8 * C_];
__device__ float g_kvs[(size_t)T_ * B_ * C_];

// ---------------------------------------------------------------------------
// 1) shortcut LIF on x:  v = v + (x - v)/2 ; spike at v>=1 ; hard reset
// ---------------------------------------------------------------------------
__global__ void lif_x_kernel(const float* __restrict__ x) {
    int idx = blockIdx.x * blockDim.x + threadIdx.x;   // (b,n,c) flat, c fastest
    float v = 0.f;
#pragma unroll
    for (int t = 0; t < T_; ++t) {
        float xv = x[(size_t)t * BNC_ + idx];
        v = v + (xv - v) * 0.5f;           // exact: (x-v)*0.5 is exact scaling
        bool s = (v >= 1.0f);
        g_xs[(size_t)t * BNC_ + idx] = s ? 1.f : 0.f;
        if (s) v = 0.f;
    }
}

// ---------------------------------------------------------------------------
// Tiled fp32 GEMM: 64x64 block tile, BK=16, 256 threads, 4x4 per thread
// ---------------------------------------------------------------------------
#define BM  64
#define BN  64
#define BK  16
#define ALD 68   // padded lds stride for transposed A tile

__global__ void gemm_qkv_kernel(const float* __restrict__ Wq,
                                const float* __restrict__ Wk,
                                const float* __restrict__ Wv,
                                const float* __restrict__ bq,
                                const float* __restrict__ bk) {
    __shared__ float As[BK * ALD];
    __shared__ float Bs[BK * BN];
    const int m0 = blockIdx.x * BM;
    const int n0 = blockIdx.y * BN;
    const int wsel = n0 >> 9;                       // 0:Wq 1:Wk 2:Wv
    const float* W = (wsel == 0) ? Wq : (wsel == 1) ? Wk : Wv;
    const int nl0 = n0 & 511;
    const int tid = threadIdx.x;
    const int tx = tid & 15, ty = tid >> 4;
    const int aRow = tid >> 2, aCol = (tid & 3) * 4;
    const int bRow = tid >> 4, bCol = (tid & 15) * 4;
    const float* Aptr = &g_xs[(size_t)(m0 + aRow) * C_ + aCol];
    const float* Bptr = &W[(size_t)bRow * C_ + nl0 + bCol];

    float acc[4][4] = {};
    for (int k0 = 0; k0 < C_; k0 += BK) {
        float4 a = *(const float4*)(Aptr + k0);
        float4 b = *(const float4*)(Bptr + (size_t)k0 * C_);
        As[(aCol + 0) * ALD + aRow] = a.x;
        As[(aCol + 1) * ALD + aRow] = a.y;
        As[(aCol + 2) * ALD + aRow] = a.z;
        As[(aCol + 3) * ALD + aRow] = a.w;
        *(float4*)&Bs[bRow * BN + bCol] = b;
        __syncthreads();
#pragma unroll
        for (int kk = 0; kk < BK; ++kk) {
            float4 av = *(const float4*)&As[kk * ALD + ty * 4];
            float4 bv = *(const float4*)&Bs[kk * BN + tx * 4];
            float ar[4] = {av.x, av.y, av.z, av.w};
            float br[4] = {bv.x, bv.y, bv.z, bv.w};
#pragma unroll
            for (int i = 0; i < 4; ++i)
#pragma unroll
                for (int j = 0; j < 4; ++j)
                    acc[i][j] += ar[i] * br[j];
        }
        __syncthreads();
    }
#pragma unroll
    for (int i = 0; i < 4; ++i) {
        int m = m0 + ty * 4 + i;
        float* yrow = &g_y[(size_t)m * QC_ + n0 + tx * 4];
#pragma unroll
        for (int j = 0; j < 4; ++j) {
            int lc = nl0 + tx * 4 + j;
            float bias = (wsel == 0) ? bq[lc] : (wsel == 1) ? bk[lc] : 0.f;
            yrow[j] = acc[i][j] + bias;
        }
    }
}

// ---------------------------------------------------------------------------
// 3) BN + LIF for q,k,v; v spikes also scattered (transposed) into d_out
// ---------------------------------------------------------------------------
__global__ void bn_lif_kernel(const float* __restrict__ bnq,
                              const float* __restrict__ bnk,
                              const float* __restrict__ bnv,
                              float* __restrict__ vout) {
    size_t idx = (size_t)blockIdx.x * blockDim.x + threadIdx.x;  // over 3*BNC_
    int sel = (int)(idx / BNC_);
    int r = (int)(idx % BNC_);
    int c = r & 511;
    int bn_i = r >> 9;                     // b*1024 + n
    const float* p = (sel == 0) ? bnq : (sel == 1) ? bnk : bnv;
    float gamma = p[c], beta = p[512 + c], mean = p[1024 + c], var = p[1536 + c];
    float rinv = 1.0f / sqrtf(var + 1e-5f);
    float* dst = (sel == 0) ? g_q : (sel == 1) ? g_k : g_v;
    int colbase = sel * 512 + c;
    float v = 0.f;
#pragma unroll
    for (int t = 0; t < T_; ++t) {
        float y = g_y[(size_t)(t * RPT_ + bn_i) * QC_ + colbase];
        // match reference rounding order: ((gamma*(y-mean))*rinv) + beta
        float u = __fadd_rn(__fmul_rn(__fmul_rn(gamma, __fadd_rn(y, -mean)), rinv), beta);
        v = v + (u - v) * 0.5f;
        bool s = (v >= 1.0f);
        float sf = s ? 1.f : 0.f;
        dst[(size_t)t * BNC_ + r] = sf;
        if (sel == 2) {
            int b = bn_i >> 10, n = bn_i & 1023, h = c >> 6, d = c & 63;
            vout[((((size_t)t * B_ + b) * H_ + h) * NN_ + n) * D_ + d] = sf;
        }
        if (s) v = 0.f;
    }
}

// ---------------------------------------------------------------------------
// 4) kv = sum_n k*v  (binary products -> exact integer sums)
// ---------------------------------------------------------------------------
__global__ void kv_partial_kernel() {
    int blk = blockIdx.x;            // blk = (t*B+b)*8 + chunk
    int chunk = blk & 7;
    int tb = blk >> 3;
    int c = threadIdx.x;             // 512 threads = (h,d)
    size_t base = (size_t)tb * NN_ * C_ + (size_t)chunk * 128 * C_ + c;
    float s = 0.f;
    for (int n = 0; n < 128; ++n) {
        size_t o = base + (size_t)n * C_;
        s += g_k[o] * g_v[o];
    }
    g_kvpart[(size_t)blk * C_ + c] = s;
}

__global__ void kv_lif_kernel() {
    int idx = blockIdx.x * blockDim.x + threadIdx.x;  // B_*C_
    int b = idx >> 9, c = idx & 511;
    float v = 0.f;
#pragma unroll
    for (int t = 0; t < T_; ++t) {
        int tb = t * B_ + b;
        float s = 0.f;
#pragma unroll
        for (int ch = 0; ch < 8; ++ch)
            s += g_kvpart[((size_t)tb * 8 + ch) * C_ + c];
        v = v + (s - v) * 0.5f;
        bool sp = (v >= 0.5f);                        // talking-heads v_th = 0.5
        g_kvs[(size_t)tb * C_ + c] = sp ? 1.f : 0.f;
        if (sp) v = 0.f;
    }
}

// ---------------------------------------------------------------------------
// 5) out GEMM: A = q * kv_spike (fused in A-tile load); epilogue = bias+BN+identity
// ---------------------------------------------------------------------------
__global__ void gemm_p_kernel(const float* __restrict__ Wp,
                              const float* __restrict__ bp,
                              const float* __restrict__ bnp,
                              const float* __restrict__ x,
                              float* __restrict__ out) {
    __shared__ float As[BK * ALD];
    __shared__ float Bs[BK * BN];
    const int m0 = blockIdx.x * BM;
    const int n0 = blockIdx.y * BN;
    const int tid = threadIdx.x;
    const int tx = tid & 15, ty = tid >> 4;
    const int aRow = tid >> 2, aCol = (tid & 3) * 4;
    const int bRow = tid >> 4, bCol = (tid & 15) * 4;
    const int tb = (m0 + aRow) >> 10;                 // m / N  = t*B + b
    const float* Aptr = &g_q[(size_t)(m0 + aRow) * C_ + aCol];
    const float* Kptr = &g_kvs[(size_t)tb * C_ + aCol];
    const float* Bptr = &Wp[(size_t)bRow * C_ + n0 + bCol];

    float acc[4][4] = {};
    for (int k0 = 0; k0 < C_; k0 += BK) {
        float4 a  = *(const float4*)(Aptr + k0);
        float4 kv = *(const float4*)(Kptr + k0);
        a.x *= kv.x; a.y *= kv.y; a.z *= kv.z; a.w *= kv.w;   // binary*binary
        float4 b = *(const float4*)(Bptr + (size_t)k0 * C_);
        As[(aCol + 0) * ALD + aRow] = a.x;
        As[(aCol + 1) * ALD + aRow] = a.y;
        As[(aCol + 2) * ALD + aRow] = a.z;
        As[(aCol + 3) * ALD + aRow] = a.w;
        *(float4*)&Bs[bRow * BN + bCol] = b;
        __syncthreads();
#pragma unroll
        for (int kk = 0; kk < BK; ++kk) {
            float4 av = *(const float4*)&As[kk * ALD + ty * 4];
            float4 bv = *(const float4*)&Bs[kk * BN + tx * 4];
            float ar[4] = {av.x, av.y, av.z, av.w};
            float br[4] = {bv.x, bv.y, bv.z, bv.w};
#pragma unroll
            for (int i = 0; i < 4; ++i)
#pragma unroll
                for (int j = 0; j < 4; ++j)
                    acc[i][j] += ar[i] * br[j];
        }
        __syncthreads();
    }
#pragma unroll
    for (int i = 0; i < 4; ++i) {
        int m = m0 + ty * 4 + i;
#pragma unroll
        for (int j = 0; j < 4; ++j) {
            int c = n0 + tx * 4 + j;
            float gamma = bnp[c], beta = bnp[512 + c], mean = bnp[1024 + c], var = bnp[1536 + c];
            float rinv = 1.0f / sqrtf(var + 1e-5f);
            float y = acc[i][j] + bp[c];
            float u = __fadd_rn(__fmul_rn(__fmul_rn(gamma, __fadd_rn(y, -mean)), rinv), beta);
            out[(size_t)m * C_ + c] = u + x[(size_t)m * C_ + c];
        }
    }
}

// ---------------------------------------------------------------------------
extern "C" void kernel_launch(void* const* d_in, const int* in_sizes, int n_in,
                              void* d_out, int out_size) {
    const float* x   = (const float*)d_in[0];
    const float* Wq  = (const float*)d_in[1];
    const float* bq  = (const float*)d_in[2];
    const float* Wk  = (const float*)d_in[3];
    const float* bk  = (const float*)d_in[4];
    const float* Wv  = (const float*)d_in[5];
    const float* Wp  = (const float*)d_in[6];
    const float* bp  = (const float*)d_in[7];
    const float* bnq = (const float*)d_in[8];
    const float* bnk = (const float*)d_in[9];
    const float* bnv = (const float*)d_in[10];
    const float* bnp = (const float*)d_in[11];
    float* out  = (float*)d_out;
    float* vout = out + (size_t)M_ * C_;   // tuple output: (out, v) concatenated

    lif_x_kernel<<<BNC_ / 256, 256>>>(x);

    dim3 gq(M_ / BM, QC_ / BN);
    gemm_qkv_kernel<<<gq, 256>>>(Wq, Wk, Wv, bq, bk);

    bn_lif_kernel<<<(3 * BNC_) / 256, 256>>>(bnq, bnk, bnv, vout);

    kv_partial_kernel<<<T_ * B_ * 8, 512>>>();
    kv_lif_kernel<<<(B_ * C_) / 256, 256>>>();

    dim3 gp(M_ / BM, C_ / BN);
    gemm_p_kernel<<<gp, 256>>>(Wp, bp, bnp, x, out);
}

// round 2
// speedup vs baseline: 2.4718x; 2.4718x over previous
#include <cuda_runtime.h>
#include <cuda_bf16.h>
#include <math.h>
#include <stdint.h>

// Problem dims
#define T_   4
#define B_   16
#define NN_  1024
#define C_   512
#define H_   8
#define D_   64
#define M_   65536        // T*B*N
#define BNC_ 8388608      // B*N*C
#define RPT_ 16384        // rows per T step (B*N)
#define QC_  1536         // fused QKV output columns

// Scratch (device globals; no allocation allowed)
__device__ __nv_bfloat16 g_xs[(size_t)M_ * C_];
__device__ float         g_y [(size_t)M_ * QC_];
__device__ __nv_bfloat16 g_q [(size_t)M_ * C_];
__device__ __nv_bfloat16 g_k [(size_t)M_ * C_];
__device__ __nv_bfloat16 g_v [(size_t)M_ * C_];
__device__ float         g_kvpart[(size_t)T_ * B_ * 8 * C_];
__device__ __nv_bfloat16 g_kvs[(size_t)T_ * B_ * C_];
// Split weights: 4 matrices (Wq,Wk,Wv,Wp) x hi/mid/lo bf16 planes
__device__ __nv_bfloat16 g_Wh[4 * C_ * C_];
__device__ __nv_bfloat16 g_Wm[4 * C_ * C_];
__device__ __nv_bfloat16 g_Wl[4 * C_ * C_];

// ---------------------------------------------------------------------------
// 0) split weights into 3 bf16 planes: w = hi + mid + lo (residual ~2^-27)
// ---------------------------------------------------------------------------
__global__ void prep_split_kernel(const float* __restrict__ Wq,
                                  const float* __restrict__ Wk,
                                  const float* __restrict__ Wv,
                                  const float* __restrict__ Wp) {
    int i = blockIdx.x * blockDim.x + threadIdx.x;   // 0 .. 4*262144
    int mat = i >> 18;
    int r = i & 262143;
    const float* src = (mat == 0) ? Wq : (mat == 1) ? Wk : (mat == 2) ? Wv : Wp;
    float w = src[r];
    __nv_bfloat16 h = __float2bfloat16_rn(w);
    float r1 = w - __bfloat162float(h);
    __nv_bfloat16 m = __float2bfloat16_rn(r1);
    float r2 = r1 - __bfloat162float(m);
    g_Wh[i] = h;
    g_Wm[i] = m;
    g_Wl[i] = __float2bfloat16_rn(r2);
}

// ---------------------------------------------------------------------------
// 1) shortcut LIF on x -> binary xs (bf16)
// ---------------------------------------------------------------------------
__global__ void lif_x_kernel(const float* __restrict__ x) {
    int idx = blockIdx.x * blockDim.x + threadIdx.x;   // (b,n,c) flat
    float v = 0.f;
#pragma unroll
    for (int t = 0; t < T_; ++t) {
        float xv = x[(size_t)t * BNC_ + idx];
        v = v + (xv - v) * 0.5f;
        bool s = (v >= 1.0f);
        g_xs[(size_t)t * BNC_ + idx] = s ? __float2bfloat16(1.f) : __float2bfloat16(0.f);
        if (s) v = 0.f;
    }
}

// ---------------------------------------------------------------------------
// Tensor-core GEMM: CTA 128x64, BK=32, 256 threads (8 warps, 4x2),
// warp tile 32x32 via mma.sync.m16n8k16 bf16, fp32 accum, 3 weight planes.
// MODE 0: A = g_xs, B = {Wq|Wk|Wv} by n0, +bias, write g_y fp32.
// MODE 1: A = g_q * g_kvs (binary AND), B = Wp, epilogue bias+BN+identity.
// ---------------------------------------------------------------------------
#define PA 40   // A smem pitch (bf16 units); 80B: 16B-aligned, conflict-free
#define PB 72   // B smem pitch; 144B

__device__ __forceinline__ void mma16816(float* c, const uint32_t* a, const uint32_t* b) {
    asm volatile(
        "mma.sync.aligned.m16n8k16.row.col.f32.bf16.bf16.f32 "
        "{%0,%1,%2,%3}, {%4,%5,%6,%7}, {%8,%9}, {%0,%1,%2,%3};"
        : "+f"(c[0]), "+f"(c[1]), "+f"(c[2]), "+f"(c[3])
        : "r"(a[0]), "r"(a[1]), "r"(a[2]), "r"(a[3]), "r"(b[0]), "r"(b[1]));
}

template <int MODE>
__global__ void gemm_tc_kernel(const float* __restrict__ bq,
                               const float* __restrict__ bk,
                               const float* __restrict__ bp,
                               const float* __restrict__ bnp,
                               const float* __restrict__ x,
                               float* __restrict__ outp) {
    __shared__ __nv_bfloat16 As[128 * PA];
    __shared__ __nv_bfloat16 Bs[3][32 * PB];

    const int m0 = blockIdx.x * 128;
    const int n0 = blockIdx.y * 64;
    const int wsel = (MODE == 0) ? (n0 >> 9) : 3;
    const int nl0 = (MODE == 0) ? (n0 & 511) : n0;
    const __nv_bfloat16* Wh = &g_Wh[(size_t)wsel * C_ * C_];
    const __nv_bfloat16* Wm = &g_Wm[(size_t)wsel * C_ * C_];
    const __nv_bfloat16* Wl = &g_Wl[(size_t)wsel * C_ * C_];

    const int tid = threadIdx.x;
    const int lane = tid & 31;
    const int warp = tid >> 5;
    const int wm = warp & 3;          // 4 warps along M (32 rows each)
    const int wn = warp >> 2;         // 2 warps along N (32 cols each)

    // smem base addresses for ldmatrix
    uint32_t sA = (uint32_t)__cvta_generic_to_shared(As);
    uint32_t sB = (uint32_t)__cvta_generic_to_shared(&Bs[0][0]);
    uint32_t aBase = sA + (uint32_t)(((wm * 32 + (lane & 15)) * PA + (lane >> 4) * 8) * 2);
    uint32_t bBase = sB + (uint32_t)((((lane & 15)) * PB + wn * 32) * 2);

    float acc[2][4][4] = {};

    for (int k0 = 0; k0 < C_; k0 += 32) {
        // ---- load A tile: 128 x 32 bf16 ----
#pragma unroll
        for (int i = 0; i < 2; ++i) {
            int idx = i * 256 + tid;
            int row = idx >> 2;
            int kc = (idx & 3) * 8;
            uint4 val;
            if (MODE == 0) {
                val = *(const uint4*)&g_xs[(size_t)(m0 + row) * C_ + k0 + kc];
            } else {
                int mr = m0 + row;
                int tb = mr >> 10;
                uint4 qa = *(const uint4*)&g_q[(size_t)mr * C_ + k0 + kc];
                uint4 kv = *(const uint4*)&g_kvs[(size_t)tb * C_ + k0 + kc];
                __nv_bfloat162* qp = (__nv_bfloat162*)&qa;
                __nv_bfloat162* kp = (__nv_bfloat162*)&kv;
#pragma unroll
                for (int e = 0; e < 4; ++e) qp[e] = __hmul2(qp[e], kp[e]);
                val = qa;
            }
            *(uint4*)&As[row * PA + kc] = val;
        }
        // ---- load B tiles: 3 planes x 32 x 64 bf16 ----
#pragma unroll
        for (int j = 0; j < 3; ++j) {
            int idx = j * 256 + tid;
            int plane = idx >> 8;
            int rem = idx & 255;
            int kr = rem >> 3;
            int nc = (rem & 7) * 8;
            const __nv_bfloat16* src = (plane == 0) ? Wh : (plane == 1) ? Wm : Wl;
            *(uint4*)&Bs[plane][kr * PB + nc] =
                *(const uint4*)&src[(size_t)(k0 + kr) * C_ + nl0 + nc];
        }
        __syncthreads();

        // ---- compute: 2 k16 steps ----
#pragma unroll
        for (int ks = 0; ks < 2; ++ks) {
            uint32_t a[2][4];
#pragma unroll
            for (int mt = 0; mt < 2; ++mt) {
                uint32_t addr = aBase + (uint32_t)((mt * 16 * PA + ks * 16) * 2);
                asm volatile(
                    "ldmatrix.sync.aligned.m8n8.x4.shared.b16 {%0,%1,%2,%3}, [%4];"
                    : "=r"(a[mt][0]), "=r"(a[mt][1]), "=r"(a[mt][2]), "=r"(a[mt][3])
                    : "r"(addr));
            }
#pragma unroll
            for (int plane = 0; plane < 3; ++plane) {
                uint32_t b[4][2];
#pragma unroll
                for (int nt = 0; nt < 4; ++nt) {
                    uint32_t addr = bBase +
                        (uint32_t)((plane * 32 * PB + ks * 16 * PB + nt * 8) * 2);
                    asm volatile(
                        "ldmatrix.sync.aligned.m8n8.x2.trans.shared.b16 {%0,%1}, [%2];"
                        : "=r"(b[nt][0]), "=r"(b[nt][1])
                        : "r"(addr));
                }
#pragma unroll
                for (int mt = 0; mt < 2; ++mt)
#pragma unroll
                    for (int nt = 0; nt < 4; ++nt)
                        mma16816(acc[mt][nt], a[mt], b[nt]);
            }
        }
        __syncthreads();
    }

    // ---- epilogue ----
#pragma unroll
    for (int mt = 0; mt < 2; ++mt) {
#pragma unroll
        for (int nt = 0; nt < 4; ++nt) {
#pragma unroll
            for (int half = 0; half < 2; ++half) {     // rows r, r+8
                int row = m0 + wm * 32 + mt * 16 + (lane >> 2) + half * 8;
                int col0 = wn * 32 + nt * 8 + (lane & 3) * 2;   // local col in [0,64)
                float c0 = acc[mt][nt][half * 2 + 0];
                float c1 = acc[mt][nt][half * 2 + 1];
                if (MODE == 0) {
                    int lc = nl0 + col0;
                    float b0 = 0.f, b1 = 0.f;
                    if (wsel == 0) { b0 = bq[lc]; b1 = bq[lc + 1]; }
                    else if (wsel == 1) { b0 = bk[lc]; b1 = bk[lc + 1]; }
                    float2 o = make_float2(c0 + b0, c1 + b1);
                    *(float2*)&g_y[(size_t)row * QC_ + n0 + col0] = o;
                } else {
                    int c = n0 + col0;
                    float2 o;
#pragma unroll
                    for (int e = 0; e < 2; ++e) {
                        int cc = c + e;
                        float gamma = bnp[cc], beta = bnp[512 + cc];
                        float mean = bnp[1024 + cc], var = bnp[1536 + cc];
                        float rinv = 1.0f / sqrtf(var + 1e-5f);
                        float yv = (e == 0 ? c0 : c1) + bp[cc];
                        float u = __fadd_rn(__fmul_rn(__fmul_rn(gamma, __fadd_rn(yv, -mean)), rinv), beta);
                        float r = u + x[(size_t)row * C_ + cc];
                        if (e == 0) o.x = r; else o.y = r;
                    }
                    *(float2*)&outp[(size_t)row * C_ + c] = o;
                }
            }
        }
    }
}

// ---------------------------------------------------------------------------
// 3) BN + LIF for q,k,v (bf16 binary outputs); v also scattered into d_out
// ---------------------------------------------------------------------------
__global__ void bn_lif_kernel(const float* __restrict__ bnq,
                              const float* __restrict__ bnk,
                              const float* __restrict__ bnv,
                              float* __restrict__ vout) {
    size_t idx = (size_t)blockIdx.x * blockDim.x + threadIdx.x;  // over 3*BNC_
    int sel = (int)(idx / BNC_);
    int r = (int)(idx % BNC_);
    int c = r & 511;
    int bn_i = r >> 9;                     // b*1024 + n
    const float* p = (sel == 0) ? bnq : (sel == 1) ? bnk : bnv;
    float gamma = p[c], beta = p[512 + c], mean = p[1024 + c], var = p[1536 + c];
    float rinv = 1.0f / sqrtf(var + 1e-5f);
    __nv_bfloat16* dst = (sel == 0) ? g_q : (sel == 1) ? g_k : g_v;
    int colbase = sel * 512 + c;
    float v = 0.f;
#pragma unroll
    for (int t = 0; t < T_; ++t) {
        float y = g_y[(size_t)(t * RPT_ + bn_i) * QC_ + colbase];
        float u = __fadd_rn(__fmul_rn(__fmul_rn(gamma, __fadd_rn(y, -mean)), rinv), beta);
        v = v + (u - v) * 0.5f;
        bool s = (v >= 1.0f);
        float sf = s ? 1.f : 0.f;
        dst[(size_t)t * BNC_ + r] = __float2bfloat16(sf);
        if (sel == 2) {
            int b = bn_i >> 10, n = bn_i & 1023, h = c >> 6, d = c & 63;
            vout[((((size_t)t * B_ + b) * H_ + h) * NN_ + n) * D_ + d] = sf;
        }
        if (s) v = 0.f;
    }
}

// ---------------------------------------------------------------------------
// 4) kv = sum_n k*v  (binary products -> exact sums) ; LIF(v_th=0.5)
// ---------------------------------------------------------------------------
__global__ void kv_partial_kernel() {
    int blk = blockIdx.x;            // blk = (t*B+b)*8 + chunk
    int chunk = blk & 7;
    int tb = blk >> 3;
    int c = threadIdx.x;             // 512 threads = (h,d)
    size_t base = (size_t)tb * NN_ * C_ + (size_t)chunk * 128 * C_ + c;
    float s = 0.f;
    for (int n = 0; n < 128; ++n) {
        size_t o = base + (size_t)n * C_;
        s += __bfloat162float(g_k[o]) * __bfloat162float(g_v[o]);
    }
    g_kvpart[(size_t)blk * C_ + c] = s;
}

__global__ void kv_lif_kernel() {
    int idx = blockIdx.x * blockDim.x + threadIdx.x;  // B_*C_
    int b = idx >> 9, c = idx & 511;
    float v = 0.f;
#pragma unroll
    for (int t = 0; t < T_; ++t) {
        int tb = t * B_ + b;
        float s = 0.f;
#pragma unroll
        for (int ch = 0; ch < 8; ++ch)
            s += g_kvpart[((size_t)tb * 8 + ch) * C_ + c];
        v = v + (s - v) * 0.5f;
        bool sp = (v >= 0.5f);
        g_kvs[(size_t)tb * C_ + c] = sp ? __float2bfloat16(1.f) : __float2bfloat16(0.f);
        if (sp) v = 0.f;
    }
}

// ---------------------------------------------------------------------------
extern "C" void kernel_launch(void* const* d_in, const int* in_sizes, int n_in,
                              void* d_out, int out_size) {
    const float* x   = (const float*)d_in[0];
    const float* Wq  = (const float*)d_in[1];
    const float* bq  = (const float*)d_in[2];
    const float* Wk  = (const float*)d_in[3];
    const float* bk  = (const float*)d_in[4];
    const float* Wv  = (const float*)d_in[5];
    const float* Wp  = (const float*)d_in[6];
    const float* bp  = (const float*)d_in[7];
    const float* bnq = (const float*)d_in[8];
    const float* bnk = (const float*)d_in[9];
    const float* bnv = (const float*)d_in[10];
    const float* bnp = (const float*)d_in[11];
    float* out  = (float*)d_out;
    float* vout = out + (size_t)M_ * C_;   // tuple output: (out, v) concatenated

    prep_split_kernel<<<4096, 256>>>(Wq, Wk, Wv, Wp);
    lif_x_kernel<<<BNC_ / 256, 256>>>(x);

    dim3 gq(M_ / 128, QC_ / 64);
    gemm_tc_kernel<0><<<gq, 256>>>(bq, bk, nullptr, nullptr, nullptr, nullptr);

    bn_lif_kernel<<<(3 * BNC_) / 256, 256>>>(bnq, bnk, bnv, vout);

    kv_partial_kernel<<<T_ * B_ * 8, 512>>>();
    kv_lif_kernel<<<(B_ * C_) / 256, 256>>>();

    dim3 gp(M_ / 128, C_ / 64);
    gemm_tc_kernel<1><<<gp, 256>>>(nullptr, nullptr, bp, bnp, x, out);
}